// round 2
// baseline (speedup 1.0000x reference)
#include <cuda_runtime.h>
#include <cuda_bf16.h>

#define N_NODES 50000
#define N_EDGES 800000
#define D 128
#define N_LAYERS 3
#define N_GRAPHS 256

// ---------------- scratch (static device globals; no runtime allocation) ----
__device__ float g_agg[N_NODES * D];   // SpMM output / GEMM input
__device__ float g_h0[N_NODES * D];    // layer output ping
__device__ float g_h1[N_NODES * D];    // layer output pong
__device__ float g_norm_out[N_NODES];
__device__ float g_norm_in[N_NODES];
__device__ int   g_deg_out[N_NODES];
__device__ int   g_deg_in[N_NODES];
__device__ int   g_rowptr[N_NODES + 1];
__device__ int   g_cursor[N_NODES];
__device__ int   g_csr_src[N_EDGES];

// ---------------- graph preprocessing --------------------------------------
__global__ void zero_deg_kernel() {
    int i = blockIdx.x * blockDim.x + threadIdx.x;
    if (i < N_NODES) { g_deg_out[i] = 0; g_deg_in[i] = 0; }
}

__global__ void count_deg_kernel(const int* __restrict__ src,
                                 const int* __restrict__ dst) {
    int i = blockIdx.x * blockDim.x + threadIdx.x;
    if (i < N_EDGES) {
        atomicAdd(&g_deg_out[src[i]], 1);
        atomicAdd(&g_deg_in[dst[i]], 1);
    }
}

__global__ void norms_kernel() {
    int i = blockIdx.x * blockDim.x + threadIdx.x;
    if (i < N_NODES) {
        g_norm_out[i] = rsqrtf((float)max(g_deg_out[i], 1));
        g_norm_in[i]  = rsqrtf((float)max(g_deg_in[i], 1));
    }
}

// exclusive scan of g_deg_in -> g_rowptr (+ init g_cursor). 1 block, 1024 thr.
__global__ void scan_kernel() {
    __shared__ int part[1024];
    const int t = threadIdx.x;
    const int CHUNK = (N_NODES + 1023) / 1024;   // 49
    int base = t * CHUNK;
    int s = 0;
    for (int i = 0; i < CHUNK; i++) {
        int idx = base + i;
        if (idx < N_NODES) s += g_deg_in[idx];
    }
    part[t] = s;
    __syncthreads();
    for (int off = 1; off < 1024; off <<= 1) {
        int v = (t >= off) ? part[t - off] : 0;
        __syncthreads();
        if (t >= off) part[t] += v;
        __syncthreads();
    }
    int run = (t == 0) ? 0 : part[t - 1];
    for (int i = 0; i < CHUNK; i++) {
        int idx = base + i;
        if (idx < N_NODES) {
            g_rowptr[idx] = run;
            g_cursor[idx] = run;
            run += g_deg_in[idx];
        }
    }
    if (t == 0) g_rowptr[N_NODES] = N_EDGES;
}

__global__ void bucket_kernel(const int* __restrict__ src,
                              const int* __restrict__ dst) {
    int i = blockIdx.x * blockDim.x + threadIdx.x;
    if (i < N_EDGES) {
        int d = dst[i];
        int pos = atomicAdd(&g_cursor[d], 1);
        g_csr_src[pos] = src[i];
    }
}

// sort each node's src list (by value) -> deterministic float summation order
__global__ void sort_csr_kernel() {
    int n = blockIdx.x * blockDim.x + threadIdx.x;
    if (n >= N_NODES) return;
    int beg = g_rowptr[n], end = g_rowptr[n + 1];
    for (int i = beg + 1; i < end; i++) {
        int v = g_csr_src[i];
        int j = i - 1;
        while (j >= beg && g_csr_src[j] > v) {
            g_csr_src[j + 1] = g_csr_src[j];
            j--;
        }
        g_csr_src[j + 1] = v;
    }
}

// ---------------- SpMM: agg[n] = norm_in[n] * sum_{s in N_in(n)} norm_out[s]*h[s]
// one warp per destination node; float4 per lane (4*32 = 128 cols)
__global__ void spmm_kernel(const float* __restrict__ feats, int in_sel) {
    const float* __restrict__ in =
        (in_sel == 0) ? feats : ((in_sel == 1) ? g_h0 : g_h1);
    int gwarp = (blockIdx.x * blockDim.x + threadIdx.x) >> 5;
    int lane = threadIdx.x & 31;
    if (gwarp >= N_NODES) return;
    int beg = g_rowptr[gwarp], end = g_rowptr[gwarp + 1];
    float4 acc = make_float4(0.f, 0.f, 0.f, 0.f);
    int e = beg;
    for (; e + 1 < end; e += 2) {
        int s0 = g_csr_src[e], s1 = g_csr_src[e + 1];
        float w0 = g_norm_out[s0], w1 = g_norm_out[s1];
        float4 v0 = ((const float4*)(in + s0 * D))[lane];
        float4 v1 = ((const float4*)(in + s1 * D))[lane];
        acc.x += w0 * v0.x + w1 * v1.x;
        acc.y += w0 * v0.y + w1 * v1.y;
        acc.z += w0 * v0.z + w1 * v1.z;
        acc.w += w0 * v0.w + w1 * v1.w;
    }
    if (e < end) {
        int s0 = g_csr_src[e];
        float w0 = g_norm_out[s0];
        float4 v0 = ((const float4*)(in + s0 * D))[lane];
        acc.x += w0 * v0.x;
        acc.y += w0 * v0.y;
        acc.z += w0 * v0.z;
        acc.w += w0 * v0.w;
    }
    float ni = g_norm_in[gwarp];
    acc.x *= ni; acc.y *= ni; acc.z *= ni; acc.w *= ni;
    ((float4*)(g_agg + gwarp * D))[lane] = acc;
}

// ---------------- fused GEMM + bias + relu: out = relu(agg @ W + b) ---------
// block = 256 threads, tile = 32 rows x 128 cols; each thread: 4x4 micro-tile
__global__ void gemm_relu_kernel(const float* __restrict__ Wl,
                                 const float* __restrict__ bl,
                                 int out_sel) {
    __shared__ float As[32][D];
    float* __restrict__ outp = (out_sel == 0) ? g_h0 : g_h1;
    int row0 = blockIdx.x * 32;
    int nrows = N_NODES - row0;
    if (nrows > 32) nrows = 32;

    // load A tile (float4 granularity): 32 rows x 32 float4
    for (int idx = threadIdx.x; idx < 32 * 32; idx += 256) {
        int r = idx >> 5;
        int c4 = idx & 31;
        float4 v = (r < nrows)
                       ? ((const float4*)(g_agg + (row0 + r) * D))[c4]
                       : make_float4(0.f, 0.f, 0.f, 0.f);
        *((float4*)&As[r][c4 * 4]) = v;
    }
    __syncthreads();

    int ty = threadIdx.x >> 5;   // 0..7  -> row group (same for whole warp)
    int tx = threadIdx.x & 31;   // 0..31 -> col group
    int r = ty * 4;

    float4 acc0 = make_float4(0.f, 0.f, 0.f, 0.f);
    float4 acc1 = acc0, acc2 = acc0, acc3 = acc0;
    const float4* __restrict__ Wv = (const float4*)Wl;

#pragma unroll 4
    for (int k = 0; k < D; k++) {
        float4 w = __ldg(&Wv[k * 32 + tx]);
        float a0 = As[r][k];
        float a1 = As[r + 1][k];
        float a2 = As[r + 2][k];
        float a3 = As[r + 3][k];
        acc0.x = fmaf(a0, w.x, acc0.x); acc0.y = fmaf(a0, w.y, acc0.y);
        acc0.z = fmaf(a0, w.z, acc0.z); acc0.w = fmaf(a0, w.w, acc0.w);
        acc1.x = fmaf(a1, w.x, acc1.x); acc1.y = fmaf(a1, w.y, acc1.y);
        acc1.z = fmaf(a1, w.z, acc1.z); acc1.w = fmaf(a1, w.w, acc1.w);
        acc2.x = fmaf(a2, w.x, acc2.x); acc2.y = fmaf(a2, w.y, acc2.y);
        acc2.z = fmaf(a2, w.z, acc2.z); acc2.w = fmaf(a2, w.w, acc2.w);
        acc3.x = fmaf(a3, w.x, acc3.x); acc3.y = fmaf(a3, w.y, acc3.y);
        acc3.z = fmaf(a3, w.z, acc3.z); acc3.w = fmaf(a3, w.w, acc3.w);
    }

    float4 bb = __ldg(&((const float4*)bl)[tx]);
    float4 accs[4] = {acc0, acc1, acc2, acc3};
#pragma unroll
    for (int i = 0; i < 4; i++) {
        int gr = row0 + r + i;
        if (gr < N_NODES) {
            float4 v;
            v.x = fmaxf(accs[i].x + bb.x, 0.f);
            v.y = fmaxf(accs[i].y + bb.y, 0.f);
            v.z = fmaxf(accs[i].z + bb.z, 0.f);
            v.w = fmaxf(accs[i].w + bb.w, 0.f);
            ((float4*)(outp + gr * D))[tx] = v;
        }
    }
}

// ---------------- pooling: per-graph mean (graph_ids is sorted) -------------
__device__ __forceinline__ int lower_bound_dev(const int* __restrict__ a,
                                               int n, int key) {
    int lo = 0, hi = n;
    while (lo < hi) {
        int mid = (lo + hi) >> 1;
        if (a[mid] < key) lo = mid + 1; else hi = mid;
    }
    return lo;
}

// one block per graph; 128 threads (one per feature column)
__global__ void pool_kernel(const int* __restrict__ gid,
                            float* __restrict__ out) {
    __shared__ int s_beg, s_end;
    int g = blockIdx.x;
    if (threadIdx.x == 0) {
        s_beg = lower_bound_dev(gid, N_NODES, g);
        s_end = lower_bound_dev(gid, N_NODES, g + 1);
    }
    __syncthreads();
    int beg = s_beg, end = s_end;
    const float* __restrict__ h = g_h0;  // final layer output lives in g_h0
    float acc = 0.f;
    for (int n = beg; n < end; n++) acc += h[n * D + threadIdx.x];
    float cnt = (float)max(end - beg, 1);
    out[g * D + threadIdx.x] = acc / cnt;
}

// ---------------- launch ----------------------------------------------------
extern "C" void kernel_launch(void* const* d_in, const int* in_sizes, int n_in,
                              void* d_out, int out_size) {
    const float* feats = (const float*)d_in[0];
    const float* W     = (const float*)d_in[1];
    const float* b     = (const float*)d_in[2];
    const int*   src   = (const int*)d_in[3];
    const int*   dst   = (const int*)d_in[4];
    const int*   gid   = (const int*)d_in[5];
    float* out = (float*)d_out;

    const int NODE_BLKS = (N_NODES + 255) / 256;   // 196
    const int EDGE_BLKS = (N_EDGES + 255) / 256;   // 3125

    // build normalized-adjacency CSR (by dst)
    zero_deg_kernel<<<NODE_BLKS, 256>>>();
    count_deg_kernel<<<EDGE_BLKS, 256>>>(src, dst);
    norms_kernel<<<NODE_BLKS, 256>>>();
    scan_kernel<<<1, 1024>>>();
    bucket_kernel<<<EDGE_BLKS, 256>>>(src, dst);
    sort_csr_kernel<<<NODE_BLKS, 256>>>();

    // 3 GraphConv layers
    const int SPMM_BLKS = N_NODES / 8;             // warp per node, 8 warps/blk
    const int GEMM_BLKS = (N_NODES + 31) / 32;     // 1563

    // layer 0: feats -> g_h0
    spmm_kernel<<<SPMM_BLKS, 256>>>(feats, 0);
    gemm_relu_kernel<<<GEMM_BLKS, 256>>>(W + 0 * D * D, b + 0 * D, 0);
    // layer 1: g_h0 -> g_h1
    spmm_kernel<<<SPMM_BLKS, 256>>>(feats, 1);
    gemm_relu_kernel<<<GEMM_BLKS, 256>>>(W + 1 * D * D, b + 1 * D, 1);
    // layer 2: g_h1 -> g_h0
    spmm_kernel<<<SPMM_BLKS, 256>>>(feats, 2);
    gemm_relu_kernel<<<GEMM_BLKS, 256>>>(W + 2 * D * D, b + 2 * D, 0);

    // readout
    pool_kernel<<<N_GRAPHS, 128>>>(gid, out);
}

// round 6
// speedup vs baseline: 2.0005x; 2.0005x over previous
#include <cuda_runtime.h>
#include <cuda_bf16.h>

#define N_NODES 50000
#define N_EDGES 800000
#define D 128
#define N_LAYERS 3
#define N_GRAPHS 256

#define SCAN_BLK 256
#define SCAN_NBLK ((N_NODES + SCAN_BLK - 1) / SCAN_BLK)   // 196
#define MAXDEG_LOCAL 128

// ---------------- scratch (static device globals) ---------------------------
__device__ float g_agg[N_NODES * D];
__device__ float g_h0[N_NODES * D];
__device__ float g_h1[N_NODES * D];
__device__ float g_norm_out[N_NODES];
__device__ float g_norm_in[N_NODES];
__device__ int   g_deg_out[N_NODES];
__device__ int   g_deg_in[N_NODES];
__device__ int   g_rowptr[N_NODES + 1];
__device__ int   g_cursor[N_NODES];
__device__ int   g_csr_src[N_EDGES];
__device__ int   g_blocksum[SCAN_NBLK];
__device__ int   g_blockoff[SCAN_NBLK];

// ---------------- graph preprocessing --------------------------------------
__global__ void zero_deg_kernel() {
    int i = blockIdx.x * blockDim.x + threadIdx.x;
    if (i < N_NODES) { g_deg_out[i] = 0; g_deg_in[i] = 0; }
}

// 4 edges per thread, vectorized index loads
__global__ void count_deg_kernel(const int* __restrict__ src,
                                 const int* __restrict__ dst) {
    int t = blockIdx.x * blockDim.x + threadIdx.x;
    int base = t * 4;
    if (base + 3 < N_EDGES) {
        int4 s = *(const int4*)(src + base);
        int4 d = *(const int4*)(dst + base);
        atomicAdd(&g_deg_out[s.x], 1); atomicAdd(&g_deg_out[s.y], 1);
        atomicAdd(&g_deg_out[s.z], 1); atomicAdd(&g_deg_out[s.w], 1);
        atomicAdd(&g_deg_in[d.x], 1);  atomicAdd(&g_deg_in[d.y], 1);
        atomicAdd(&g_deg_in[d.z], 1);  atomicAdd(&g_deg_in[d.w], 1);
    } else {
        for (int i = base; i < N_EDGES; i++) {
            atomicAdd(&g_deg_out[src[i]], 1);
            atomicAdd(&g_deg_in[dst[i]], 1);
        }
    }
}

// stage A: per-block sums of deg_in + fused norm computation
__global__ void scanA_kernel() {
    __shared__ int warp_sum[SCAN_BLK / 32];
    int i = blockIdx.x * SCAN_BLK + threadIdx.x;
    int v = 0;
    if (i < N_NODES) {
        int din = g_deg_in[i];
        v = din;
        g_norm_out[i] = rsqrtf((float)max(g_deg_out[i], 1));
        g_norm_in[i]  = rsqrtf((float)max(din, 1));
    }
    // warp reduce
    int s = v;
#pragma unroll
    for (int off = 16; off > 0; off >>= 1)
        s += __shfl_down_sync(0xffffffffu, s, off);
    if ((threadIdx.x & 31) == 0) warp_sum[threadIdx.x >> 5] = s;
    __syncthreads();
    if (threadIdx.x < SCAN_BLK / 32) {
        int ws = warp_sum[threadIdx.x];
#pragma unroll
        for (int off = SCAN_BLK / 64; off > 0; off >>= 1)
            ws += __shfl_down_sync(0xffffffffu, ws, off);
        if (threadIdx.x == 0) g_blocksum[blockIdx.x] = ws;
    }
}

// stage B: exclusive scan of 196 block sums (1 block, 256 threads)
__global__ void scanB_kernel() {
    __shared__ int sm[SCAN_NBLK];
    int t = threadIdx.x;
    int v = (t < SCAN_NBLK) ? g_blocksum[t] : 0;
    if (t < SCAN_NBLK) sm[t] = v;
    __syncthreads();
    for (int off = 1; off < SCAN_NBLK; off <<= 1) {
        int add = 0;
        if (t < SCAN_NBLK && t >= off) add = sm[t - off];
        __syncthreads();
        if (t < SCAN_NBLK && t >= off) sm[t] += add;
        __syncthreads();
    }
    if (t < SCAN_NBLK) g_blockoff[t] = sm[t] - v;  // exclusive
    if (t == 0) g_rowptr[N_NODES] = N_EDGES;
}

// stage C: block-level exclusive scan + offset -> rowptr, cursor
__global__ void scanC_kernel() {
    __shared__ int sm[SCAN_BLK];
    int i = blockIdx.x * SCAN_BLK + threadIdx.x;
    int t = threadIdx.x;
    int v = (i < N_NODES) ? g_deg_in[i] : 0;
    sm[t] = v;
    __syncthreads();
#pragma unroll
    for (int off = 1; off < SCAN_BLK; off <<= 1) {
        int add = (t >= off) ? sm[t - off] : 0;
        __syncthreads();
        sm[t] += add;
        __syncthreads();
    }
    if (i < N_NODES) {
        int rp = g_blockoff[blockIdx.x] + sm[t] - v;  // exclusive
        g_rowptr[i] = rp;
        g_cursor[i] = rp;
    }
}

__global__ void bucket_kernel(const int* __restrict__ src,
                              const int* __restrict__ dst) {
    int i = blockIdx.x * blockDim.x + threadIdx.x;
    if (i < N_EDGES) {
        int d = dst[i];
        int pos = atomicAdd(&g_cursor[d], 1);
        g_csr_src[pos] = src[i];
    }
}

// deterministic order: sort each node's src list by value, staged in local mem
__global__ void sort_csr_kernel() {
    int n = blockIdx.x * blockDim.x + threadIdx.x;
    if (n >= N_NODES) return;
    int beg = g_rowptr[n], end = g_rowptr[n + 1];
    int d = end - beg;
    if (d <= 1) return;
    if (d <= MAXDEG_LOCAL) {
        int buf[MAXDEG_LOCAL];
        for (int i = 0; i < d; i++) buf[i] = g_csr_src[beg + i];
        for (int i = 1; i < d; i++) {
            int v = buf[i];
            int j = i - 1;
            while (j >= 0 && buf[j] > v) { buf[j + 1] = buf[j]; j--; }
            buf[j + 1] = v;
        }
        for (int i = 0; i < d; i++) g_csr_src[beg + i] = buf[i];
    } else {
        for (int i = beg + 1; i < end; i++) {
            int v = g_csr_src[i];
            int j = i - 1;
            while (j >= beg && g_csr_src[j] > v) {
                g_csr_src[j + 1] = g_csr_src[j];
                j--;
            }
            g_csr_src[j + 1] = v;
        }
    }
}

// ---------------- SpMM: agg[n] = norm_in[n] * sum norm_out[s]*h[s] ----------
// one warp per destination node; float4 per lane; 4-edge unroll for MLP
__global__ void spmm_kernel(const float* __restrict__ feats, int in_sel) {
    const float* __restrict__ in =
        (in_sel == 0) ? feats : ((in_sel == 1) ? g_h0 : g_h1);
    int gwarp = (blockIdx.x * blockDim.x + threadIdx.x) >> 5;
    int lane = threadIdx.x & 31;
    if (gwarp >= N_NODES) return;
    int beg = g_rowptr[gwarp], end = g_rowptr[gwarp + 1];
    float4 acc = make_float4(0.f, 0.f, 0.f, 0.f);
    int e = beg;
    for (; e + 3 < end; e += 4) {
        int s0 = g_csr_src[e],     s1 = g_csr_src[e + 1];
        int s2 = g_csr_src[e + 2], s3 = g_csr_src[e + 3];
        float w0 = g_norm_out[s0], w1 = g_norm_out[s1];
        float w2 = g_norm_out[s2], w3 = g_norm_out[s3];
        float4 v0 = ((const float4*)(in + s0 * D))[lane];
        float4 v1 = ((const float4*)(in + s1 * D))[lane];
        float4 v2 = ((const float4*)(in + s2 * D))[lane];
        float4 v3 = ((const float4*)(in + s3 * D))[lane];
        acc.x += w0 * v0.x + w1 * v1.x + w2 * v2.x + w3 * v3.x;
        acc.y += w0 * v0.y + w1 * v1.y + w2 * v2.y + w3 * v3.y;
        acc.z += w0 * v0.z + w1 * v1.z + w2 * v2.z + w3 * v3.z;
        acc.w += w0 * v0.w + w1 * v1.w + w2 * v2.w + w3 * v3.w;
    }
    for (; e < end; e++) {
        int s0 = g_csr_src[e];
        float w0 = g_norm_out[s0];
        float4 v0 = ((const float4*)(in + s0 * D))[lane];
        acc.x += w0 * v0.x; acc.y += w0 * v0.y;
        acc.z += w0 * v0.z; acc.w += w0 * v0.w;
    }
    float ni = g_norm_in[gwarp];
    acc.x *= ni; acc.y *= ni; acc.z *= ni; acc.w *= ni;
    ((float4*)(g_agg + gwarp * D))[lane] = acc;
}

// ---------------- fused GEMM + bias + relu: out = relu(agg @ W + b) ---------
// block = 256 thr; tile 32 rows x 128 cols; thread: 4 rows x 4 cols; k in f4
__global__ void gemm_relu_kernel(const float* __restrict__ Wl,
                                 const float* __restrict__ bl,
                                 int out_sel) {
    __shared__ float4 As4[32][32];   // [row][k/4]
    float* __restrict__ outp = (out_sel == 0) ? g_h0 : g_h1;
    int row0 = blockIdx.x * 32;
    int nrows = N_NODES - row0;
    if (nrows > 32) nrows = 32;

    for (int idx = threadIdx.x; idx < 32 * 32; idx += 256) {
        int r = idx >> 5;
        int c4 = idx & 31;
        float4 v = (r < nrows)
                       ? ((const float4*)(g_agg + (row0 + r) * D))[c4]
                       : make_float4(0.f, 0.f, 0.f, 0.f);
        As4[r][c4] = v;
    }
    __syncthreads();

    int ty = threadIdx.x >> 5;   // 0..7 (uniform per warp)
    int tx = threadIdx.x & 31;   // 0..31 -> column group (float4)
    int r = ty * 4;

    float4 acc[4];
#pragma unroll
    for (int i = 0; i < 4; i++) acc[i] = make_float4(0.f, 0.f, 0.f, 0.f);
    const float4* __restrict__ Wv = (const float4*)Wl;

#pragma unroll 8
    for (int k4 = 0; k4 < 32; k4++) {
        float4 w0 = __ldg(&Wv[(4 * k4 + 0) * 32 + tx]);
        float4 w1 = __ldg(&Wv[(4 * k4 + 1) * 32 + tx]);
        float4 w2 = __ldg(&Wv[(4 * k4 + 2) * 32 + tx]);
        float4 w3 = __ldg(&Wv[(4 * k4 + 3) * 32 + tx]);
#pragma unroll
        for (int i = 0; i < 4; i++) {
            float4 a = As4[r + i][k4];
            acc[i].x = fmaf(a.x, w0.x, acc[i].x);
            acc[i].y = fmaf(a.x, w0.y, acc[i].y);
            acc[i].z = fmaf(a.x, w0.z, acc[i].z);
            acc[i].w = fmaf(a.x, w0.w, acc[i].w);
            acc[i].x = fmaf(a.y, w1.x, acc[i].x);
            acc[i].y = fmaf(a.y, w1.y, acc[i].y);
            acc[i].z = fmaf(a.y, w1.z, acc[i].z);
            acc[i].w = fmaf(a.y, w1.w, acc[i].w);
            acc[i].x = fmaf(a.z, w2.x, acc[i].x);
            acc[i].y = fmaf(a.z, w2.y, acc[i].y);
            acc[i].z = fmaf(a.z, w2.z, acc[i].z);
            acc[i].w = fmaf(a.z, w2.w, acc[i].w);
            acc[i].x = fmaf(a.w, w3.x, acc[i].x);
            acc[i].y = fmaf(a.w, w3.y, acc[i].y);
            acc[i].z = fmaf(a.w, w3.z, acc[i].z);
            acc[i].w = fmaf(a.w, w3.w, acc[i].w);
        }
    }

    float4 bb = __ldg(&((const float4*)bl)[tx]);
#pragma unroll
    for (int i = 0; i < 4; i++) {
        int gr = row0 + r + i;
        if (gr < N_NODES) {
            float4 v;
            v.x = fmaxf(acc[i].x + bb.x, 0.f);
            v.y = fmaxf(acc[i].y + bb.y, 0.f);
            v.z = fmaxf(acc[i].z + bb.z, 0.f);
            v.w = fmaxf(acc[i].w + bb.w, 0.f);
            ((float4*)(outp + gr * D))[tx] = v;
        }
    }
}

// ---------------- pooling: per-graph mean (graph_ids sorted) ----------------
__device__ __forceinline__ int lower_bound_dev(const int* __restrict__ a,
                                               int n, int key) {
    int lo = 0, hi = n;
    while (lo < hi) {
        int mid = (lo + hi) >> 1;
        if (a[mid] < key) lo = mid + 1; else hi = mid;
    }
    return lo;
}

__global__ void pool_kernel(const int* __restrict__ gid,
                            float* __restrict__ out) {
    __shared__ int s_beg, s_end;
    int g = blockIdx.x;
    if (threadIdx.x == 0) {
        s_beg = lower_bound_dev(gid, N_NODES, g);
        s_end = lower_bound_dev(gid, N_NODES, g + 1);
    }
    __syncthreads();
    int beg = s_beg, end = s_end;
    const float* __restrict__ h = g_h0;  // final layer output
    float acc = 0.f;
    for (int n = beg; n < end; n++) acc += h[n * D + threadIdx.x];
    float cnt = (float)max(end - beg, 1);
    out[g * D + threadIdx.x] = acc / cnt;
}

// ---------------- launch ----------------------------------------------------
extern "C" void kernel_launch(void* const* d_in, const int* in_sizes, int n_in,
                              void* d_out, int out_size) {
    const float* feats = (const float*)d_in[0];
    const float* W     = (const float*)d_in[1];
    const float* b     = (const float*)d_in[2];
    const int*   src   = (const int*)d_in[3];
    const int*   dst   = (const int*)d_in[4];
    const int*   gid   = (const int*)d_in[5];
    float* out = (float*)d_out;

    const int NODE_BLKS = (N_NODES + 255) / 256;           // 196
    const int EDGE_BLKS = (N_EDGES + 255) / 256;           // 3125
    const int CNT_BLKS  = (N_EDGES / 4 + 255) / 256;       // 782

    zero_deg_kernel<<<NODE_BLKS, 256>>>();
    count_deg_kernel<<<CNT_BLKS, 256>>>(src, dst);
    scanA_kernel<<<SCAN_NBLK, SCAN_BLK>>>();
    scanB_kernel<<<1, 256>>>();
    scanC_kernel<<<SCAN_NBLK, SCAN_BLK>>>();
    bucket_kernel<<<EDGE_BLKS, 256>>>(src, dst);
    sort_csr_kernel<<<NODE_BLKS, 256>>>();

    const int SPMM_BLKS = N_NODES / 8;                     // 6250
    const int GEMM_BLKS = (N_NODES + 31) / 32;             // 1563

    spmm_kernel<<<SPMM_BLKS, 256>>>(feats, 0);
    gemm_relu_kernel<<<GEMM_BLKS, 256>>>(W + 0 * D * D, b + 0 * D, 0);
    spmm_kernel<<<SPMM_BLKS, 256>>>(feats, 1);
    gemm_relu_kernel<<<GEMM_BLKS, 256>>>(W + 1 * D * D, b + 1 * D, 1);
    spmm_kernel<<<SPMM_BLKS, 256>>>(feats, 2);
    gemm_relu_kernel<<<GEMM_BLKS, 256>>>(W + 2 * D * D, b + 2 * D, 0);

    pool_kernel<<<N_GRAPHS, 128>>>(gid, out);
}